// round 13
// baseline (speedup 1.0000x reference)
#include <cuda_runtime.h>
#include <cuda_fp16.h>
#include <cstdint>

// ---------------------------------------------------------------------------
// HouseholderFlow via warp-level mma.sync (HMMA, base sm_103 ISA).
// R5: fp16 2-pass split GEMM.
//   Weights pre-scaled Ws' = 50*W, split Whi+Wlo (fp16 pair ~ 2^-22 accurate).
//   Activations v quantized to single fp16 (2^-11).
//   C = A16 @ (Whi + Wlo)^T  (2 MMA passes, fp32 acc);  v = C/50 + bias.
//   z <- z - 2 v (v.z)/||v||^2 per row (scale-invariant in v).
// ---------------------------------------------------------------------------

#define BM 128
#define BN 64
#define BK 64
#define NTHREADS 256
#define NSTAGES 3

#define OFF_A  0
#define OFF_B0 16384
#define OFF_B1 24576
#define STAGE_BYTES 32768
#define SMEM_TOTAL (NSTAGES * STAGE_BYTES)

#define MAXB 8192
#define MAXL 2048
#define MAXNF 8
#define WSCALE 50.0f
#define WSCALE_INV (1.0f / 50.0f)

__device__ __half g_w_hi[(size_t)MAXNF * MAXL * MAXL];
__device__ __half g_w_lo[(size_t)MAXNF * MAXL * MAXL];
__device__ __half g_a16[2][(size_t)MAXB * MAXL];
__device__ float g_v[(size_t)MAXB * MAXL];

// ---------------- PTX helpers (base ISA only) ----------------

__device__ __forceinline__ uint32_t smem_u32(const void* p) {
    uint32_t a;
    asm("{ .reg .u64 t; cvta.to.shared.u64 t, %1; cvt.u32.u64 %0, t; }"
        : "=r"(a) : "l"(p));
    return a;
}

__device__ __forceinline__ void cp_async_16(uint32_t saddr, const void* gaddr) {
    asm volatile("cp.async.cg.shared.global [%0], [%1], 16;" :: "r"(saddr), "l"(gaddr));
}
#define CP_COMMIT() asm volatile("cp.async.commit_group;" ::: "memory")
#define CP_WAIT(n)  asm volatile("cp.async.wait_group %0;" :: "n"(n) : "memory")

__device__ __forceinline__ void ldsm_x4(uint32_t* r, uint32_t addr) {
    asm volatile("ldmatrix.sync.aligned.m8n8.x4.shared.b16 {%0,%1,%2,%3}, [%4];"
                 : "=r"(r[0]), "=r"(r[1]), "=r"(r[2]), "=r"(r[3]) : "r"(addr));
}

__device__ __forceinline__ void mma_fp16(float* d, const uint32_t* a, const uint32_t* b) {
    asm volatile(
        "mma.sync.aligned.m16n8k16.row.col.f32.f16.f16.f32 "
        "{%0,%1,%2,%3}, {%4,%5,%6,%7}, {%8,%9}, {%0,%1,%2,%3};"
        : "+f"(d[0]), "+f"(d[1]), "+f"(d[2]), "+f"(d[3])
        : "r"(a[0]), "r"(a[1]), "r"(a[2]), "r"(a[3]), "r"(b[0]), "r"(b[1]));
}

// ---------------- GEMM kernel ----------------
// C[m,n] = sum_k A16[m,k]*(Whi[n,k]+Wlo[n,k]); out v = C/50 + bias[n].
// Writes v as fp32 (Vout) and fp16 (OutA16) for the next GEMM.
__global__ __launch_bounds__(NTHREADS, 2)
void mma_fp16x2_kernel(const __half* __restrict__ A16,
                       const __half* __restrict__ Whi,
                       const __half* __restrict__ Wlo,
                       const float* __restrict__ bias,
                       float* __restrict__ Vout,
                       __half* __restrict__ OutA16,
                       int M, int N, int K) {
    extern __shared__ __align__(1024) char smem_raw[];
    const uint32_t sb = smem_u32(smem_raw);

    const int tid = threadIdx.x;
    const int lane = tid & 31;
    const int wid = tid >> 5;
    const int wm = wid & 3;   // 4 warps along M: 4*32 = 128
    const int wn = wid >> 2;  // 2 warps along N: 2*32 = 64
    const int bm = blockIdx.y * BM;
    const int bn = blockIdx.x * BN;

    // ---- cp.async stage loader: rows x 64 fp16 (128B), XOR swizzle ----
    auto load_stage = [&](int k0, int s) {
        const uint32_t st = sb + (uint32_t)s * STAGE_BYTES;
#pragma unroll
        for (int it = 0; it < 4; ++it) {              // A: 128 rows * 8 chunks
            int q = tid + it * NTHREADS;
            int row = q >> 3, kc = q & 7;
            uint32_t so = (uint32_t)(row * 128 + ((kc ^ (row & 7)) << 4));
            size_t ge = (size_t)(bm + row) * K + k0 + kc * 8;
            cp_async_16(st + OFF_A + so, A16 + ge);
        }
#pragma unroll
        for (int it = 0; it < 2; ++it) {              // B: 64 rows * 8 chunks
            int q = tid + it * NTHREADS;
            int row = q >> 3, kc = q & 7;
            uint32_t so = (uint32_t)(row * 128 + ((kc ^ (row & 7)) << 4));
            size_t ge = (size_t)(bn + row) * K + k0 + kc * 8;
            cp_async_16(st + OFF_B0 + so, Whi + ge);
            cp_async_16(st + OFF_B1 + so, Wlo + ge);
        }
    };

    // ---- per-lane ldmatrix address components ----
    int aRow[2], bRow[2];
#pragma unroll
    for (int mi = 0; mi < 2; ++mi) aRow[mi] = wm * 32 + mi * 16 + (lane & 15);
#pragma unroll
    for (int g = 0; g < 2; ++g)
        bRow[g] = wn * 32 + g * 16 + ((lane >> 4) << 3) + (lane & 7);
    const int aCh = lane >> 4;
    const int bCh = (lane >> 3) & 1;

    float acc[2][4][4];
#pragma unroll
    for (int mi = 0; mi < 2; ++mi)
#pragma unroll
        for (int ni = 0; ni < 4; ++ni)
#pragma unroll
            for (int r = 0; r < 4; ++r) acc[mi][ni][r] = 0.f;

    // double-buffered fragments
    uint32_t af[2][2][4], bh[2][2][4], bl[2][2][4];

    auto load_frags = [&](uint32_t st, int k, int b) {
#pragma unroll
        for (int mi = 0; mi < 2; ++mi) {
            uint32_t off = (uint32_t)(aRow[mi] * 128 +
                            (((2 * k + aCh) ^ (aRow[mi] & 7)) << 4));
            ldsm_x4(af[b][mi], st + OFF_A + off);
        }
#pragma unroll
        for (int g = 0; g < 2; ++g) {
            uint32_t off = (uint32_t)(bRow[g] * 128 +
                            (((2 * k + bCh) ^ (bRow[g] & 7)) << 4));
            ldsm_x4(bh[b][g], st + OFF_B0 + off);
            ldsm_x4(bl[b][g], st + OFF_B1 + off);
        }
    };

    auto do_mmas = [&](int b) {
        // pass-major: 8 independent MMAs between accumulator reuses
#pragma unroll
        for (int mi = 0; mi < 2; ++mi)
#pragma unroll
            for (int ni = 0; ni < 4; ++ni)
                mma_fp16(acc[mi][ni], af[b][mi], &bh[b][ni >> 1][(ni & 1) * 2]);
#pragma unroll
        for (int mi = 0; mi < 2; ++mi)
#pragma unroll
            for (int ni = 0; ni < 4; ++ni)
                mma_fp16(acc[mi][ni], af[b][mi], &bl[b][ni >> 1][(ni & 1) * 2]);
    };

    const int NS = K / BK;
    load_stage(0, 0);  CP_COMMIT();
    load_stage(BK, 1); CP_COMMIT();

    for (int i = 0; i < NS; ++i) {
        const int s = i % NSTAGES;
        const uint32_t stc = sb + (uint32_t)s * STAGE_BYTES;
        CP_WAIT(1);            // per-thread: group for stage i complete
        __syncthreads();       // all threads' stage-i data visible; slot (i-1)%3 free
        if (i + 2 < NS) load_stage((i + 2) * BK, (i + 2) % NSTAGES);
        CP_COMMIT();           // always commit (empty groups keep numbering uniform)

        load_frags(stc, 0, 0);
#pragma unroll
        for (int k = 0; k < 4; ++k) {
            if (k < 3) load_frags(stc, k + 1, (k + 1) & 1);
            do_mmas(k & 1);
        }
    }

    // ---- epilogue: scale, bias add, write fp32 + fp16 ----
    const int quad = lane >> 2;
    const int tc = (lane & 3) * 2;
#pragma unroll
    for (int mi = 0; mi < 2; ++mi) {
#pragma unroll
        for (int ni = 0; ni < 4; ++ni) {
            const int col = bn + wn * 32 + ni * 8 + tc;
            const int r0 = bm + wm * 32 + mi * 16 + quad;
            const float2 b2 = *reinterpret_cast<const float2*>(bias + col);
            float2 o0, o1;
            o0.x = acc[mi][ni][0] * WSCALE_INV + b2.x;
            o0.y = acc[mi][ni][1] * WSCALE_INV + b2.y;
            o1.x = acc[mi][ni][2] * WSCALE_INV + b2.x;
            o1.y = acc[mi][ni][3] * WSCALE_INV + b2.y;
            *reinterpret_cast<float2*>(Vout + (size_t)r0 * N + col) = o0;
            *reinterpret_cast<float2*>(Vout + (size_t)(r0 + 8) * N + col) = o1;

            __half2 h0, h1;
            h0.x = __float2half_rn(o0.x); h0.y = __float2half_rn(o0.y);
            h1.x = __float2half_rn(o1.x); h1.y = __float2half_rn(o1.y);
            *reinterpret_cast<__half2*>(OutA16 + (size_t)r0 * N + col) = h0;
            *reinterpret_cast<__half2*>(OutA16 + (size_t)(r0 + 8) * N + col) = h1;
        }
    }
}

// ---------------- fp32 -> scaled fp16 hi/lo split (weights) ----------------
__global__ __launch_bounds__(256)
void split_w_kernel(const float* __restrict__ src,
                    __half* __restrict__ hi,
                    __half* __restrict__ lo,
                    size_t n) {
    size_t i = ((size_t)blockIdx.x * 256 + threadIdx.x) * 4;
    if (i >= n) return;
    float4 x = *reinterpret_cast<const float4*>(src + i);
    x.x *= WSCALE; x.y *= WSCALE; x.z *= WSCALE; x.w *= WSCALE;
    __half2 hh0, hh1, ll0, ll1;
    hh0.x = __float2half_rn(x.x); hh0.y = __float2half_rn(x.y);
    hh1.x = __float2half_rn(x.z); hh1.y = __float2half_rn(x.w);
    ll0.x = __float2half_rn(x.x - __half2float(hh0.x));
    ll0.y = __float2half_rn(x.y - __half2float(hh0.y));
    ll1.x = __float2half_rn(x.z - __half2float(hh1.x));
    ll1.y = __float2half_rn(x.w - __half2float(hh1.y));
    *reinterpret_cast<__half2*>(hi + i) = hh0;
    *reinterpret_cast<__half2*>(hi + i + 2) = hh1;
    *reinterpret_cast<__half2*>(lo + i) = ll0;
    *reinterpret_cast<__half2*>(lo + i + 2) = ll1;
}

// ---------------- fp32 -> fp16 convert (activations) ----------------
__global__ __launch_bounds__(256)
void cvt_fp16_kernel(const float* __restrict__ src,
                     __half* __restrict__ dst, size_t n) {
    size_t i = ((size_t)blockIdx.x * 256 + threadIdx.x) * 4;
    if (i >= n) return;
    float4 x = *reinterpret_cast<const float4*>(src + i);
    __half2 h0, h1;
    h0.x = __float2half_rn(x.x); h0.y = __float2half_rn(x.y);
    h1.x = __float2half_rn(x.z); h1.y = __float2half_rn(x.w);
    *reinterpret_cast<__half2*>(dst + i) = h0;
    *reinterpret_cast<__half2*>(dst + i + 2) = h1;
}

// ---------------- Householder reflection ----------------
__global__ __launch_bounds__(256)
void hflow_kernel(const float* __restrict__ V,
                  const float* __restrict__ Zin,
                  float* __restrict__ Zout, int L) {
    const size_t base = (size_t)blockIdx.x * L;
    const float4* v4 = reinterpret_cast<const float4*>(V + base);
    const float4* z4 = reinterpret_cast<const float4*>(Zin + base);
    float4* o4 = reinterpret_cast<float4*>(Zout + base);
    const int n4 = L >> 2;

    float4 vr[4], zr[4];
    float vz = 0.f, vv = 0.f;
    int cnt = 0;
    for (int idx = threadIdx.x; idx < n4; idx += 256) {
        const float4 v = v4[idx];
        const float4 z = z4[idx];
        vr[cnt] = v; zr[cnt] = z; ++cnt;
        vz += v.x * z.x + v.y * z.y + v.z * z.z + v.w * z.w;
        vv += v.x * v.x + v.y * v.y + v.z * v.z + v.w * v.w;
    }
#pragma unroll
    for (int off = 16; off > 0; off >>= 1) {
        vz += __shfl_xor_sync(0xffffffffu, vz, off);
        vv += __shfl_xor_sync(0xffffffffu, vv, off);
    }
    __shared__ float svz[8], svv[8];
    const int w = threadIdx.x >> 5;
    if ((threadIdx.x & 31) == 0) { svz[w] = vz; svv[w] = vv; }
    __syncthreads();
    float tvz = 0.f, tvv = 0.f;
#pragma unroll
    for (int i = 0; i < 8; ++i) { tvz += svz[i]; tvv += svv[i]; }
    const float s = -2.0f * tvz / tvv;

    cnt = 0;
    for (int idx = threadIdx.x; idx < n4; idx += 256) {
        const float4 v = vr[cnt];
        const float4 z = zr[cnt]; ++cnt;
        o4[idx] = make_float4(z.x + s * v.x, z.y + s * v.y,
                              z.z + s * v.z, z.w + s * v.w);
    }
}

// ---------------- host launcher ----------------
extern "C" void kernel_launch(void* const* d_in, const int* in_sizes, int n_in,
                              void* d_out, int out_size) {
    const float* z      = (const float*)d_in[0];  // [B, L]
    const float* h_last = (const float*)d_in[1];  // [B, H]
    const float* W0     = (const float*)d_in[2];  // [L, H]
    const float* b0     = (const float*)d_in[3];  // [L]
    const float* Ws     = (const float*)d_in[4];  // [NF-1, L, L]
    const float* bs     = (const float*)d_in[5];  // [NF-1, L]

    const int L = in_sizes[3];
    const int B = in_sizes[0] / L;
    const int H = in_sizes[2] / L;
    const int nsteps = in_sizes[5] / L;  // NF - 1

    float* zout = (float*)d_out;

    void *pwh, *pwl, *pa, *pv;
    cudaGetSymbolAddress(&pwh, g_w_hi);
    cudaGetSymbolAddress(&pwl, g_w_lo);
    cudaGetSymbolAddress(&pa, g_a16);
    cudaGetSymbolAddress(&pv, g_v);
    __half* whi = (__half*)pwh;
    __half* wlo = (__half*)pwl;
    __half* a16[2] = {(__half*)pa, (__half*)pa + (size_t)MAXB * MAXL};
    float* v = (float*)pv;

    cudaFuncSetAttribute(mma_fp16x2_kernel,
                         cudaFuncAttributeMaxDynamicSharedMemorySize, SMEM_TOTAL);

    // weight splits (scaled by 50) + first activation convert
    {
        size_t n0 = (size_t)L * H;
        split_w_kernel<<<(unsigned)(n0 / 4 / 256), 256>>>(W0, whi, wlo, n0);
        size_t nw = (size_t)nsteps * L * L;
        split_w_kernel<<<(unsigned)(nw / 4 / 256), 256>>>(Ws, whi + n0, wlo + n0, nw);
        size_t na = (size_t)B * H;
        cvt_fp16_kernel<<<(unsigned)(na / 4 / 256), 256>>>(h_last, a16[0], na);
    }

    const dim3 gblock(NTHREADS);
    const dim3 ggrid(L / BN, B / BM);

    int cur = 0;
    for (int j = 0; j <= nsteps; ++j) {
        const int K = (j == 0) ? H : L;
        const __half* wh = whi + ((j == 0) ? 0 : (size_t)L * H + (size_t)(j - 1) * L * L);
        const __half* wl = wlo + ((j == 0) ? 0 : (size_t)L * H + (size_t)(j - 1) * L * L);
        const float* bias = (j == 0) ? b0 : bs + (size_t)(j - 1) * L;
        const int nxt = cur ^ 1;

        mma_fp16x2_kernel<<<ggrid, gblock, SMEM_TOTAL>>>(
            a16[cur], wh, wl, bias, v, a16[nxt], B, L, K);
        hflow_kernel<<<B, 256>>>(v, (j == 0) ? z : zout, zout, L);
        cur = nxt;
    }
}